// round 2
// baseline (speedup 1.0000x reference)
#include <cuda_runtime.h>
#include <cuda_bf16.h>
#include <cstdint>

// Problem constants
#define BATCH 8192
#define FEAT  512
#define DEG   32
#define F2    1024   // 2*FEAT
#define F3    1536   // 3*FEAT
#define BN_EPS 1e-5f

// Output layout (floats): agg, to_feats, gen, raw, env_gen, env_raw
#define OFF_AGG   0
#define OFF_TO    (BATCH*FEAT)                       // 4194304
#define OFF_GEN   (OFF_TO   + BATCH*F3)              // 16777216
#define OFF_RAW   (OFF_GEN  + BATCH*F2)              // 25165824
#define OFF_EGEN  (OFF_RAW  + BATCH*F2)              // 33554432
#define OFF_ERAW  (OFF_EGEN + BATCH*F2)              // 41943040

// ---------------- scratch (__device__ globals; no allocations) --------------
__device__ float g_cat [(size_t)BATCH * F2];   // [self | agg]      32 MB
__device__ float g_env [(size_t)BATCH * FEAT]; // env_agg           16 MB
__device__ float g_xhat[(size_t)BATCH * F3];   // normalized feats  48 MB
__device__ float g_s[F3];
__device__ float g_t[F3];

// ---------------------------------------------------------------------------
// Gather + mean-pool. One block per batch row, 128 threads, float4 per thread.
// neigh_idx[:,0] == nodes, so row 0 is the self row.
// ---------------------------------------------------------------------------
__global__ void gather_kernel(const float* __restrict__ feat,
                              const int*  __restrict__ neigh,
                              float* __restrict__ aggO)
{
    const int m = blockIdx.x;
    __shared__ int idx[DEG];
    if (threadIdx.x < DEG) idx[threadIdx.x] = neigh[(size_t)m * DEG + threadIdx.x];
    __syncthreads();

    const int c = threadIdx.x * 4;   // 128 threads * 4 = 512 cols

    float4 v0 = *(const float4*)(feat + (size_t)idx[0] * FEAT + c);
    float sx = v0.x, sy = v0.y, sz = v0.z, sw = v0.w;
#pragma unroll 8
    for (int j = 1; j < DEG; j++) {
        float4 v = *(const float4*)(feat + (size_t)idx[j] * FEAT + c);
        sx += v.x; sy += v.y; sz += v.z; sw += v.w;
    }
    const float r32 = 1.0f / 32.0f;
    const float r31 = 1.0f / 31.0f;
    float4 agg = make_float4(sx * r32, sy * r32, sz * r32, sw * r32);
    float4 env = make_float4((sx - v0.x) * r31, (sy - v0.y) * r31,
                             (sz - v0.z) * r31, (sw - v0.w) * r31);

    *(float4*)(g_cat + (size_t)m * F2 + c)        = v0;   // self half
    *(float4*)(g_cat + (size_t)m * F2 + FEAT + c) = agg;  // agg half
    *(float4*)(aggO  + (size_t)m * FEAT + c)      = agg;  // output agg_feats
    *(float4*)(g_env + (size_t)m * FEAT + c)      = env;  // env_agg
}

// ---------------------------------------------------------------------------
// SGEMM 128x128x16, 256 threads, 8x8 per thread (2x2 quads of 4x4).
// MODE 0: C0 = A@B (raw), C1 = relu(A@B) (gen)
// MODE 1: C0 = relu(A@B)
// M,N multiples of 128; K multiple of 16.
// ---------------------------------------------------------------------------
#define BM 128
#define BN 128
#define BK 16

template <int MODE>
__global__ void __launch_bounds__(256, 2)
sgemm128(const float* __restrict__ A, const float* __restrict__ B,
         float* __restrict__ C0, float* __restrict__ C1,
         int K, int lda, int ldb, int ldc)
{
    __shared__ float As[BK][BM + 4];   // +4 keeps float4 alignment of rows
    __shared__ float Bs[BK][BN];

    const int tid = threadIdx.x;
    const int tx = tid & 15;          // 0..15 -> N
    const int ty = tid >> 4;          // 0..15 -> M

    const int arow  = tid >> 2;       // 0..63
    const int acol  = (tid & 3) << 2; // 0,4,8,12
    const int brow  = tid >> 5;       // 0..7
    const int bcol  = (tid & 31) << 2;// 0..124

    const float* Ap = A + (size_t)(blockIdx.y * BM) * lda;
    const float* Bp = B + blockIdx.x * BN;

    float acc[2][2][4][4] = {};

    for (int k0 = 0; k0 < K; k0 += BK) {
        // A tile -> SMEM transposed
#pragma unroll
        for (int r = 0; r < 2; r++) {
            int row = arow + r * 64;
            float4 v = *(const float4*)(Ap + (size_t)row * lda + k0 + acol);
            As[acol + 0][row] = v.x;
            As[acol + 1][row] = v.y;
            As[acol + 2][row] = v.z;
            As[acol + 3][row] = v.w;
        }
        // B tile -> SMEM direct
#pragma unroll
        for (int r = 0; r < 2; r++) {
            int row = brow + r * 8;
            *(float4*)&Bs[row][bcol] =
                *(const float4*)(Bp + (size_t)(k0 + row) * ldb + bcol);
        }
        __syncthreads();

#pragma unroll
        for (int kk = 0; kk < BK; kk++) {
            float a[2][4], b[2][4];
            *(float4*)a[0] = *(const float4*)&As[kk][ty * 4];
            *(float4*)a[1] = *(const float4*)&As[kk][ty * 4 + 64];
            *(float4*)b[0] = *(const float4*)&Bs[kk][tx * 4];
            *(float4*)b[1] = *(const float4*)&Bs[kk][tx * 4 + 64];
#pragma unroll
            for (int iw = 0; iw < 2; iw++)
#pragma unroll
                for (int i = 0; i < 4; i++)
#pragma unroll
                    for (int jw = 0; jw < 2; jw++)
#pragma unroll
                        for (int j = 0; j < 4; j++)
                            acc[iw][jw][i][j] += a[iw][i] * b[jw][j];
        }
        __syncthreads();
    }

    // Epilogue
#pragma unroll
    for (int iw = 0; iw < 2; iw++) {
#pragma unroll
        for (int i = 0; i < 4; i++) {
            size_t row = (size_t)blockIdx.y * BM + iw * 64 + ty * 4 + i;
#pragma unroll
            for (int jw = 0; jw < 2; jw++) {
                int col = blockIdx.x * BN + jw * 64 + tx * 4;
                float4 v = make_float4(acc[iw][jw][i][0], acc[iw][jw][i][1],
                                       acc[iw][jw][i][2], acc[iw][jw][i][3]);
                if (MODE == 0) {
                    *(float4*)(C0 + row * ldc + col) = v;   // raw
                    float4 g = make_float4(fmaxf(v.x, 0.f), fmaxf(v.y, 0.f),
                                           fmaxf(v.z, 0.f), fmaxf(v.w, 0.f));
                    *(float4*)(C1 + row * ldc + col) = g;   // gen = relu(raw)
                } else {
                    float4 g = make_float4(fmaxf(v.x, 0.f), fmaxf(v.y, 0.f),
                                           fmaxf(v.z, 0.f), fmaxf(v.w, 0.f));
                    *(float4*)(C0 + row * ldc + col) = g;
                }
            }
        }
    }
}

// ---------------------------------------------------------------------------
// BatchNorm statistics: per-column mean/var over 8192 rows.
// feats = [agg (stride 512) | gen (stride 1024)].
// One block per 32 columns; 256 threads = 32 cols x 8 row-lanes.
// ---------------------------------------------------------------------------
__global__ void bn_stats_kernel(const float* __restrict__ agg,
                                const float* __restrict__ gen,
                                const float* __restrict__ gamma,
                                const float* __restrict__ beta)
{
    const int c0 = blockIdx.x * 32;
    const int cx = threadIdx.x & 31;
    const int ry = threadIdx.x >> 5;   // 0..7
    const int c  = c0 + cx;

    const float* base;
    int stride;
    if (c0 < FEAT) { base = agg + c;          stride = FEAT; }
    else           { base = gen + (c - FEAT); stride = F2;   }

    float sum = 0.f, sq = 0.f;
#pragma unroll 4
    for (int r = ry; r < BATCH; r += 8) {
        float v = base[(size_t)r * stride];
        sum += v; sq += v * v;
    }

    __shared__ float ssum[8][32], ssq[8][32];
    ssum[ry][cx] = sum; ssq[ry][cx] = sq;
    __syncthreads();
    if (ry == 0) {
#pragma unroll
        for (int r = 1; r < 8; r++) { sum += ssum[r][cx]; sq += ssq[r][cx]; }
        const float inv = 1.0f / (float)BATCH;
        float mean = sum * inv;
        float var  = sq * inv - mean * mean;
        float s = gamma[c] * rsqrtf(var + BN_EPS);
        g_s[c] = s;
        g_t[c] = beta[c] - mean * s;
    }
}

// ---------------------------------------------------------------------------
// xhat = feats * s + t   -> GEMM3 becomes a plain GEMM + relu.
// ---------------------------------------------------------------------------
__global__ void xhat_kernel(const float* __restrict__ agg,
                            const float* __restrict__ gen)
{
    size_t t = (size_t)blockIdx.x * blockDim.x + threadIdx.x; // float4 index
    int m = (int)(t / (F3 / 4));
    int c = (int)(t % (F3 / 4)) * 4;

    float4 v;
    if (c < FEAT) v = *(const float4*)(agg + (size_t)m * FEAT + c);
    else          v = *(const float4*)(gen + (size_t)m * F2 + (c - FEAT));
    float4 s4 = *(const float4*)(g_s + c);
    float4 t4 = *(const float4*)(g_t + c);
    float4 o = make_float4(v.x * s4.x + t4.x, v.y * s4.y + t4.y,
                           v.z * s4.z + t4.z, v.w * s4.w + t4.w);
    *(float4*)(g_xhat + (size_t)m * F3 + c) = o;
}

// ---------------------------------------------------------------------------
extern "C" void kernel_launch(void* const* d_in, const int* in_sizes, int n_in,
                              void* d_out, int out_size)
{
    const float* feat  = (const float*)d_in[0];
    const float* Wg    = (const float*)d_in[1];
    const float* W1    = (const float*)d_in[2];
    const float* gamma = (const float*)d_in[3];
    const float* beta  = (const float*)d_in[4];
    // d_in[5] = nodes (redundant: neigh_idx[:,0] == nodes)
    const int*   neigh = (const int*)d_in[6];

    float* out   = (float*)d_out;
    float* aggO  = out + OFF_AGG;
    float* toO   = out + OFF_TO;
    float* genO  = out + OFF_GEN;
    float* rawO  = out + OFF_RAW;
    float* egenO = out + OFF_EGEN;
    float* erawO = out + OFF_ERAW;

    float *p_cat, *p_env, *p_xhat;
    cudaGetSymbolAddress((void**)&p_cat,  g_cat);
    cudaGetSymbolAddress((void**)&p_env,  g_env);
    cudaGetSymbolAddress((void**)&p_xhat, g_xhat);

    // 1) gather + pooling
    gather_kernel<<<BATCH, 128>>>(feat, neigh, aggO);

    // 2) raw/gen = cat @ W_gen        [8192,1024] x [1024,1024]
    sgemm128<0><<<dim3(F2 / BN, BATCH / BM), 256>>>(
        p_cat, Wg, rawO, genO, F2, F2, F2, F2);

    // 3) env_raw/env_gen = env_agg @ W_gen[512:,:]   [8192,512] x [512,1024]
    sgemm128<0><<<dim3(F2 / BN, BATCH / BM), 256>>>(
        p_env, Wg + (size_t)FEAT * F2, erawO, egenO, FEAT, FEAT, F2, F2);

    // 4) BN statistics over [agg | gen]
    bn_stats_kernel<<<F3 / 32, 256>>>(aggO, genO, gamma, beta);

    // 5) xhat = feats * s + t
    {
        size_t total4 = (size_t)BATCH * F3 / 4;
        xhat_kernel<<<(unsigned)(total4 / 256), 256>>>(aggO, genO);
    }

    // 6) to_feats = relu(xhat @ weight1)   [8192,1536] x [1536,1536]
    sgemm128<1><<<dim3(F3 / BN, BATCH / BM), 256>>>(
        p_xhat, W1, toO, nullptr, F3, F3, F3, F3);

    (void)in_sizes; (void)n_in; (void)out_size;
}

// round 5
// speedup vs baseline: 2.5231x; 2.5231x over previous
#include <cuda_runtime.h>
#include <cuda_bf16.h>
#include <cstdint>

// Problem constants
#define BATCH 8192
#define FEAT  512
#define DEG   32
#define F2    1024   // 2*FEAT
#define F3    1536   // 3*FEAT
#define BN_EPS 1e-5f

// Output layout (floats): agg, to_feats, gen, raw, env_gen, env_raw
#define OFF_AGG   0
#define OFF_TO    (BATCH*FEAT)
#define OFF_GEN   (OFF_TO   + BATCH*F3)
#define OFF_RAW   (OFF_GEN  + BATCH*F2)
#define OFF_EGEN  (OFF_RAW  + BATCH*F2)
#define OFF_ERAW  (OFF_EGEN + BATCH*F2)

// ---------------- scratch (__device__ globals; no allocations) --------------
__device__ float g_cat [(size_t)BATCH * F2];   // [self | agg] tf32-rounded
__device__ float g_env [(size_t)BATCH * FEAT]; // env_agg tf32-rounded
__device__ float g_xhat[(size_t)BATCH * F3];   // normalized feats tf32-rounded
__device__ float g_Wg2 [(size_t)F2 * F2];      // W_gen tf32-rounded, [K][N]
__device__ float g_W12 [(size_t)F3 * F3];      // weight1 tf32-rounded, [K][N]
__device__ float g_s[F3];
__device__ float g_t[F3];
__device__ float g_bnsum[F3];
__device__ float g_bnsq[F3];

// ------------------------------- helpers ------------------------------------
__device__ __forceinline__ uint32_t smem_u32(const void* p) {
    uint32_t a;
    asm("{ .reg .u64 t; cvta.to.shared.u64 t, %1; cvt.u32.u64 %0, t; }"
        : "=r"(a) : "l"(p));
    return a;
}
__device__ __forceinline__ float tf32r(float v) {
    uint32_t u;
    asm("cvt.rna.tf32.f32 %0, %1;" : "=r"(u) : "f"(v));
    return __uint_as_float(u);
}
__device__ __forceinline__ float4 tf32r4(float4 v) {
    return make_float4(tf32r(v.x), tf32r(v.y), tf32r(v.z), tf32r(v.w));
}
__device__ __forceinline__ void cp_async16(uint32_t dst, const void* src) {
    asm volatile("cp.async.cg.shared.global [%0], [%1], 16;" :: "r"(dst), "l"(src));
}
#define CP_COMMIT() asm volatile("cp.async.commit_group;" ::: "memory")
#define CP_WAIT(n)  asm volatile("cp.async.wait_group %0;" :: "n"(n) : "memory")

__device__ __forceinline__ void mma_tf32(float* c, const float* a, const float* b) {
    asm volatile(
        "mma.sync.aligned.m16n8k8.row.col.f32.tf32.tf32.f32 "
        "{%0,%1,%2,%3}, {%4,%5,%6,%7}, {%8,%9}, {%0,%1,%2,%3};"
        : "+f"(c[0]), "+f"(c[1]), "+f"(c[2]), "+f"(c[3])
        : "r"(__float_as_uint(a[0])), "r"(__float_as_uint(a[1])),
          "r"(__float_as_uint(a[2])), "r"(__float_as_uint(a[3])),
          "r"(__float_as_uint(b[0])), "r"(__float_as_uint(b[1])));
}

// ---------------------------------------------------------------------------
// Gather + mean-pool (also writes tf32-rounded staging for GEMMs).
// ---------------------------------------------------------------------------
__global__ void gather_kernel(const float* __restrict__ feat,
                              const int*  __restrict__ neigh,
                              float* __restrict__ aggO)
{
    const int m = blockIdx.x;
    __shared__ int idx[DEG];
    if (threadIdx.x < DEG) idx[threadIdx.x] = neigh[(size_t)m * DEG + threadIdx.x];
    __syncthreads();

    const int c = threadIdx.x * 4;

    float4 v0 = *(const float4*)(feat + (size_t)idx[0] * FEAT + c);
    float sx = v0.x, sy = v0.y, sz = v0.z, sw = v0.w;
#pragma unroll 8
    for (int j = 1; j < DEG; j++) {
        float4 v = *(const float4*)(feat + (size_t)idx[j] * FEAT + c);
        sx += v.x; sy += v.y; sz += v.z; sw += v.w;
    }
    const float r32 = 1.0f / 32.0f;
    const float r31 = 1.0f / 31.0f;
    float4 agg = make_float4(sx * r32, sy * r32, sz * r32, sw * r32);
    float4 env = make_float4((sx - v0.x) * r31, (sy - v0.y) * r31,
                             (sz - v0.z) * r31, (sw - v0.w) * r31);

    *(float4*)(g_cat + (size_t)m * F2 + c)        = tf32r4(v0);
    *(float4*)(g_cat + (size_t)m * F2 + FEAT + c) = tf32r4(agg);
    *(float4*)(aggO  + (size_t)m * FEAT + c)      = agg;     // exact output
    *(float4*)(g_env + (size_t)m * FEAT + c)      = tf32r4(env);
}

// ---------------------------------------------------------------------------
// Elementwise tf32 round-copy (weights stay in native [K][N] layout).
// ---------------------------------------------------------------------------
__global__ void round_copy(const float* __restrict__ src, float* __restrict__ dst,
                           size_t n4)
{
    size_t i = (size_t)blockIdx.x * blockDim.x + threadIdx.x;
    if (i < n4) ((float4*)dst)[i] = tf32r4(((const float4*)src)[i]);
}

// ---------------------------------------------------------------------------
// tf32 mma.sync GEMM: block 128x128x32, 256 thr, 8 warps (2x4), warp 64x32.
// A [M,K] row-major (tf32-rounded), B [K,N] row-major (tf32-rounded).
// MODE 0: C0 = A@B (raw), C1 = relu.  MODE 1: C0 = relu(A@B).
// 3-stage cp.async pipeline.
// SMEM: As[128][36] (pad), Bs[32][132] (pad) per stage.
// ---------------------------------------------------------------------------
#define BM 128
#define BN 128
#define BK 32
#define NSTAGE 3
#define A_STRIDE 36
#define B_STRIDE 132
#define A_BYTES (BM * A_STRIDE * 4)          // 18432
#define STAGE_BYTES (A_BYTES + BK * B_STRIDE * 4)   // 35328

template <int MODE>
__global__ void __launch_bounds__(256)
mma_gemm(const float* __restrict__ A, const float* __restrict__ B,
         float* __restrict__ C0, float* __restrict__ C1,
         int K, int lda, int ldb, int ldc)
{
    extern __shared__ __align__(16) char smem[];
    const uint32_t sbase = smem_u32(smem);
    const int tid = threadIdx.x, wid = tid >> 5, lane = tid & 31;
    const int wm = wid >> 2, wn = wid & 3;       // warp grid 2 x 4
    const int lr = lane >> 2, lc = lane & 3;
    const int m0 = blockIdx.y * BM, n0 = blockIdx.x * BN;
    const int T = K / BK;

    const float* Ap = A + (size_t)m0 * lda;
    const float* Bp = B + n0;

    auto load_stage = [&](int blk, int s) {
        const uint32_t a_s = sbase + (uint32_t)s * STAGE_BYTES;
        const uint32_t b_s = a_s + A_BYTES;
        const int k0 = blk * BK;
#pragma unroll
        for (int u = 0; u < 4; u++) {            // A: 1024 16B chunks
            int ch = tid + u * 256;
            int row = ch >> 3, c16 = ch & 7;
            cp_async16(a_s + (uint32_t)row * (A_STRIDE * 4) + c16 * 16,
                       Ap + (size_t)row * lda + k0 + c16 * 4);
        }
#pragma unroll
        for (int u = 0; u < 4; u++) {            // B: 1024 16B chunks
            int ch = tid + u * 256;
            int row = ch >> 5, c16 = ch & 31;
            cp_async16(b_s + (uint32_t)row * (B_STRIDE * 4) + c16 * 16,
                       Bp + (size_t)(k0 + row) * ldb + c16 * 4);
        }
    };

    float acc[4][4][4];
#pragma unroll
    for (int i = 0; i < 4; i++)
#pragma unroll
        for (int j = 0; j < 4; j++)
#pragma unroll
            for (int r = 0; r < 4; r++) acc[i][j][r] = 0.f;

    load_stage(0, 0); CP_COMMIT();
    load_stage(1, 1); CP_COMMIT();

    for (int i = 0; i < T; i++) {
        if (i + 2 < T) load_stage(i + 2, (i + 2) % NSTAGE);
        CP_COMMIT();
        CP_WAIT(2);
        __syncthreads();

        const float* As = (const float*)(smem + (size_t)(i % NSTAGE) * STAGE_BYTES);
        const float* Bs = As + BM * A_STRIDE / 1 - 0 + 0;   // placeholder
        Bs = (const float*)((const char*)As + A_BYTES);

#pragma unroll
        for (int k8 = 0; k8 < 4; k8++) {
            const int kk = k8 * 8;
            float a[4][4], b[4][2];
#pragma unroll
            for (int mi = 0; mi < 4; mi++) {
                const int am = wm * 64 + mi * 16 + lr;
                a[mi][0] = As[(size_t)am * A_STRIDE + kk + lc];
                a[mi][1] = As[(size_t)(am + 8) * A_STRIDE + kk + lc];
                a[mi][2] = As[(size_t)am * A_STRIDE + kk + 4 + lc];
                a[mi][3] = As[(size_t)(am + 8) * A_STRIDE + kk + 4 + lc];
            }
#pragma unroll
            for (int ni = 0; ni < 4; ni++) {
                const int bn = wn * 32 + ni * 8 + lr;
                b[ni][0] = Bs[(size_t)(kk + lc) * B_STRIDE + bn];
                b[ni][1] = Bs[(size_t)(kk + 4 + lc) * B_STRIDE + bn];
            }
#pragma unroll
            for (int mi = 0; mi < 4; mi++)
#pragma unroll
                for (int ni = 0; ni < 4; ni++)
                    mma_tf32(acc[mi][ni], a[mi], b[ni]);
        }
        __syncthreads();
    }

    // Epilogue: c0,c1 -> (row, col..col+1); c2,c3 -> (row+8, ...)
#pragma unroll
    for (int mi = 0; mi < 4; mi++) {
#pragma unroll
        for (int half = 0; half < 2; half++) {
            const size_t row = (size_t)m0 + wm * 64 + mi * 16 + lr + half * 8;
#pragma unroll
            for (int ni = 0; ni < 4; ni++) {
                const int col = n0 + wn * 32 + ni * 8 + lc * 2;
                float x = acc[mi][ni][half * 2 + 0];
                float y = acc[mi][ni][half * 2 + 1];
                if (MODE == 0) {
                    *(float2*)(C0 + row * ldc + col) = make_float2(x, y);
                    *(float2*)(C1 + row * ldc + col) =
                        make_float2(fmaxf(x, 0.f), fmaxf(y, 0.f));
                } else {
                    *(float2*)(C0 + row * ldc + col) =
                        make_float2(fmaxf(x, 0.f), fmaxf(y, 0.f));
                }
            }
        }
    }
}

// ---------------------------------------------------------------------------
// BN stats: 2D grid (48 col-blocks x 16 row-chunks), atomics into g_bnsum/sq.
// ---------------------------------------------------------------------------
__global__ void bn_stats_kernel(const float* __restrict__ agg,
                                const float* __restrict__ gen)
{
    const int c0 = blockIdx.x * 32;
    const int cx = threadIdx.x & 31;
    const int ry = threadIdx.x >> 5;   // 0..7
    const int c  = c0 + cx;

    const float* base;
    int stride;
    if (c0 < FEAT) { base = agg + c;          stride = FEAT; }
    else           { base = gen + (c - FEAT); stride = F2;   }

    const int r0 = blockIdx.y * 512;
    float sum = 0.f, sq = 0.f;
#pragma unroll 8
    for (int r = r0 + ry; r < r0 + 512; r += 8) {
        float v = base[(size_t)r * stride];
        sum += v; sq += v * v;
    }
    __shared__ float ssum[8][32], ssq[8][32];
    ssum[ry][cx] = sum; ssq[ry][cx] = sq;
    __syncthreads();
    if (ry == 0) {
#pragma unroll
        for (int r = 1; r < 8; r++) { sum += ssum[r][cx]; sq += ssq[r][cx]; }
        atomicAdd(&g_bnsum[c], sum);
        atomicAdd(&g_bnsq[c], sq);
    }
}

__global__ void bn_finalize(const float* __restrict__ gamma,
                            const float* __restrict__ beta)
{
    int c = blockIdx.x * blockDim.x + threadIdx.x;
    if (c >= F3) return;
    const float inv = 1.0f / (float)BATCH;
    float mean = g_bnsum[c] * inv;
    float var  = g_bnsq[c] * inv - mean * mean;
    float s = gamma[c] * rsqrtf(var + BN_EPS);
    g_s[c] = s;
    g_t[c] = beta[c] - mean * s;
}

// ---------------------------------------------------------------------------
// xhat = round_tf32(feats * s + t)
// ---------------------------------------------------------------------------
__global__ void xhat_kernel(const float* __restrict__ agg,
                            const float* __restrict__ gen)
{
    size_t t = (size_t)blockIdx.x * blockDim.x + threadIdx.x;
    int m = (int)(t / (F3 / 4));
    int c = (int)(t % (F3 / 4)) * 4;

    float4 v;
    if (c < FEAT) v = *(const float4*)(agg + (size_t)m * FEAT + c);
    else          v = *(const float4*)(gen + (size_t)m * F2 + (c - FEAT));
    float4 s4 = *(const float4*)(g_s + c);
    float4 t4 = *(const float4*)(g_t + c);
    float4 o = make_float4(v.x * s4.x + t4.x, v.y * s4.y + t4.y,
                           v.z * s4.z + t4.z, v.w * s4.w + t4.w);
    *(float4*)(g_xhat + (size_t)m * F3 + c) = tf32r4(o);
}

// ---------------------------------------------------------------------------
extern "C" void kernel_launch(void* const* d_in, const int* in_sizes, int n_in,
                              void* d_out, int out_size)
{
    const float* feat  = (const float*)d_in[0];
    const float* Wg    = (const float*)d_in[1];
    const float* W1    = (const float*)d_in[2];
    const float* gamma = (const float*)d_in[3];
    const float* beta  = (const float*)d_in[4];
    const int*   neigh = (const int*)d_in[6];

    float* out   = (float*)d_out;
    float* aggO  = out + OFF_AGG;
    float* toO   = out + OFF_TO;
    float* genO  = out + OFF_GEN;
    float* rawO  = out + OFF_RAW;
    float* egenO = out + OFF_EGEN;
    float* erawO = out + OFF_ERAW;

    float *p_cat, *p_env, *p_xhat, *p_Wg2, *p_W12, *p_sum, *p_sq;
    cudaGetSymbolAddress((void**)&p_cat,  g_cat);
    cudaGetSymbolAddress((void**)&p_env,  g_env);
    cudaGetSymbolAddress((void**)&p_xhat, g_xhat);
    cudaGetSymbolAddress((void**)&p_Wg2,  g_Wg2);
    cudaGetSymbolAddress((void**)&p_W12,  g_W12);
    cudaGetSymbolAddress((void**)&p_sum,  g_bnsum);
    cudaGetSymbolAddress((void**)&p_sq,   g_bnsq);

    const int smem_bytes = NSTAGE * STAGE_BYTES;   // 105984
    cudaFuncSetAttribute(mma_gemm<0>, cudaFuncAttributeMaxDynamicSharedMemorySize, smem_bytes);
    cudaFuncSetAttribute(mma_gemm<1>, cudaFuncAttributeMaxDynamicSharedMemorySize, smem_bytes);

    // 0) weight tf32 round-copies + BN accumulator reset
    round_copy<<<(unsigned)((size_t)F2 * F2 / 4 / 256), 256>>>(Wg, p_Wg2, (size_t)F2 * F2 / 4);
    round_copy<<<(unsigned)((size_t)F3 * F3 / 4 / 256), 256>>>(W1, p_W12, (size_t)F3 * F3 / 4);
    cudaMemsetAsync(p_sum, 0, F3 * sizeof(float));
    cudaMemsetAsync(p_sq,  0, F3 * sizeof(float));

    // 1) gather + pooling (+tf32-rounded staging)
    gather_kernel<<<BATCH, 128>>>(feat, neigh, aggO);

    // 2) raw/gen = cat @ W_gen          [8192,1024] x [1024,1024]
    mma_gemm<0><<<dim3(F2/BN, BATCH/BM), 256, smem_bytes>>>(
        p_cat, p_Wg2, rawO, genO, F2, F2, F2, F2);

    // 3) env_raw/env_gen = env @ W_gen[512:,:]   [8192,512] x [512,1024]
    mma_gemm<0><<<dim3(F2/BN, BATCH/BM), 256, smem_bytes>>>(
        p_env, p_Wg2 + (size_t)FEAT * F2, erawO, egenO, FEAT, FEAT, F2, F2);

    // 4) BN statistics + finalize
    bn_stats_kernel<<<dim3(F3/32, 16), 256>>>(aggO, genO);
    bn_finalize<<<F3/256, 256>>>(gamma, beta);

    // 5) xhat = feats*s + t (tf32-rounded)
    xhat_kernel<<<(unsigned)((size_t)BATCH * F3 / 4 / 256), 256>>>(aggO, genO);

    // 6) to_feats = relu(xhat @ weight1)   [8192,1536] x [1536,1536]
    mma_gemm<1><<<dim3(F3/BN, BATCH/BM), 256, smem_bytes>>>(
        p_xhat, p_W12, toO, nullptr, F3, F3, F3, F3);

    (void)in_sizes; (void)n_in; (void)out_size;
}

// round 6
// speedup vs baseline: 3.0250x; 1.1989x over previous
#include <cuda_runtime.h>
#include <cuda_bf16.h>
#include <cstdint>

// Problem constants
#define BATCH 8192
#define FEAT  512
#define DEG   32
#define F2    1024   // 2*FEAT
#define F3    1536   // 3*FEAT
#define BN_EPS 1e-5f

// Output layout (floats): agg, to_feats, gen, raw, env_gen, env_raw
#define OFF_AGG   0
#define OFF_TO    (BATCH*FEAT)
#define OFF_GEN   (OFF_TO   + BATCH*F3)
#define OFF_RAW   (OFF_GEN  + BATCH*F2)
#define OFF_EGEN  (OFF_RAW  + BATCH*F2)
#define OFF_ERAW  (OFF_EGEN + BATCH*F2)

// ---------------- scratch (__device__ globals; no allocations) --------------
__device__ float g_cat [(size_t)BATCH * F2];   // [self | agg] tf32-rounded
__device__ float g_env [(size_t)BATCH * FEAT]; // env_agg tf32-rounded
__device__ float g_xhat[(size_t)BATCH * F3];   // normalized feats tf32-rounded
__device__ float g_Wg2 [(size_t)F2 * F2];      // W_gen tf32-rounded, [K][N]
__device__ float g_W12 [(size_t)F3 * F3];      // weight1 tf32-rounded, [K][N]
__device__ float g_s[F3];
__device__ float g_t[F3];
__device__ float g_bnsum[F3];
__device__ float g_bnsq[F3];

// ------------------------------- helpers ------------------------------------
__device__ __forceinline__ float tf32r(float v) {
    uint32_t u;
    asm("cvt.rna.tf32.f32 %0, %1;" : "=r"(u) : "f"(v));
    return __uint_as_float(u);
}
__device__ __forceinline__ float4 tf32r4(float4 v) {
    return make_float4(tf32r(v.x), tf32r(v.y), tf32r(v.z), tf32r(v.w));
}
__device__ __forceinline__ uint32_t smem_u32(const void* p) {
    uint32_t a;
    asm("{ .reg .u64 t; cvta.to.shared.u64 t, %1; cvt.u32.u64 %0, t; }"
        : "=r"(a) : "l"(p));
    return a;
}
__device__ __forceinline__ void cp_async16(uint32_t dst, const void* src) {
    asm volatile("cp.async.cg.shared.global [%0], [%1], 16;" :: "r"(dst), "l"(src));
}
#define CP_COMMIT() asm volatile("cp.async.commit_group;" ::: "memory")
#define CP_WAIT(n)  asm volatile("cp.async.wait_group %0;" :: "n"(n) : "memory")

__device__ __forceinline__ void mma_tf32(float* c, const float* a, const float* b) {
    asm volatile(
        "mma.sync.aligned.m16n8k8.row.col.f32.tf32.tf32.f32 "
        "{%0,%1,%2,%3}, {%4,%5,%6,%7}, {%8,%9}, {%0,%1,%2,%3};"
        : "+f"(c[0]), "+f"(c[1]), "+f"(c[2]), "+f"(c[3])
        : "r"(__float_as_uint(a[0])), "r"(__float_as_uint(a[1])),
          "r"(__float_as_uint(a[2])), "r"(__float_as_uint(a[3])),
          "r"(__float_as_uint(b[0])), "r"(__float_as_uint(b[1])));
}

// ---------------------------------------------------------------------------
// Gather + mean-pool (also writes tf32-rounded staging for GEMMs).
// ---------------------------------------------------------------------------
__global__ void gather_kernel(const float* __restrict__ feat,
                              const int*  __restrict__ neigh,
                              float* __restrict__ aggO)
{
    const int m = blockIdx.x;
    __shared__ int idx[DEG];
    if (threadIdx.x < DEG) idx[threadIdx.x] = neigh[(size_t)m * DEG + threadIdx.x];
    __syncthreads();

    const int c = threadIdx.x * 4;

    float4 v0 = *(const float4*)(feat + (size_t)idx[0] * FEAT + c);
    float sx = v0.x, sy = v0.y, sz = v0.z, sw = v0.w;
#pragma unroll 8
    for (int j = 1; j < DEG; j++) {
        float4 v = *(const float4*)(feat + (size_t)idx[j] * FEAT + c);
        sx += v.x; sy += v.y; sz += v.z; sw += v.w;
    }
    const float r32 = 1.0f / 32.0f;
    const float r31 = 1.0f / 31.0f;
    float4 agg = make_float4(sx * r32, sy * r32, sz * r32, sw * r32);
    float4 env = make_float4((sx - v0.x) * r31, (sy - v0.y) * r31,
                             (sz - v0.z) * r31, (sw - v0.w) * r31);

    *(float4*)(g_cat + (size_t)m * F2 + c)        = tf32r4(v0);
    *(float4*)(g_cat + (size_t)m * F2 + FEAT + c) = tf32r4(agg);
    *(float4*)(aggO  + (size_t)m * FEAT + c)      = agg;     // exact output
    *(float4*)(g_env + (size_t)m * FEAT + c)      = tf32r4(env);
}

// ---------------------------------------------------------------------------
// Elementwise tf32 round-copy (weights stay in native [K][N] layout).
// ---------------------------------------------------------------------------
__global__ void round_copy(const float* __restrict__ src, float* __restrict__ dst,
                           size_t n4)
{
    size_t i = (size_t)blockIdx.x * blockDim.x + threadIdx.x;
    if (i < n4) ((float4*)dst)[i] = tf32r4(((const float4*)src)[i]);
}

// ---------------------------------------------------------------------------
// tf32 mma.sync GEMM: block 128x256x32, 256 thr, 8 warps (2x4), warp 64x64.
// A [M,K] row-major (tf32-rounded), B [K,N] row-major (tf32-rounded).
// MODE 0: C0 = A@B (raw), C1 = relu.  MODE 1: C0 = relu(A@B).
// 3-stage cp.async pipeline.
// SMEM per stage: As[128][36] pad, Bs[32][264] pad (both conflict-free).
// ---------------------------------------------------------------------------
#define BM 128
#define BN 256
#define BK 32
#define NSTAGE 3
#define A_STRIDE 36
#define B_STRIDE 264
#define A_BYTES (BM * A_STRIDE * 4)                 // 18432
#define STAGE_BYTES (A_BYTES + BK * B_STRIDE * 4)   // 52224

template <int MODE>
__global__ void __launch_bounds__(256)
mma_gemm(const float* __restrict__ A, const float* __restrict__ B,
         float* __restrict__ C0, float* __restrict__ C1,
         int K, int lda, int ldb, int ldc)
{
    extern __shared__ __align__(16) char smem[];
    const uint32_t sbase = smem_u32(smem);
    const int tid = threadIdx.x, wid = tid >> 5, lane = tid & 31;
    const int wm = wid >> 2, wn = wid & 3;       // warp grid 2 x 4
    const int lr = lane >> 2, lc = lane & 3;
    const int m0 = blockIdx.y * BM, n0 = blockIdx.x * BN;
    const int T = K / BK;

    const float* Ap = A + (size_t)m0 * lda;
    const float* Bp = B + n0;

    auto load_stage = [&](int blk, int s) {
        const uint32_t a_s = sbase + (uint32_t)s * STAGE_BYTES;
        const uint32_t b_s = a_s + A_BYTES;
        const int k0 = blk * BK;
#pragma unroll
        for (int u = 0; u < 4; u++) {            // A: 1024 16B chunks
            int ch = tid + u * 256;
            int row = ch >> 3, c16 = ch & 7;
            cp_async16(a_s + (uint32_t)row * (A_STRIDE * 4) + c16 * 16,
                       Ap + (size_t)row * lda + k0 + c16 * 4);
        }
#pragma unroll
        for (int u = 0; u < 8; u++) {            // B: 2048 16B chunks
            int ch = tid + u * 256;
            int row = ch >> 6, c16 = ch & 63;
            cp_async16(b_s + (uint32_t)row * (B_STRIDE * 4) + c16 * 16,
                       Bp + (size_t)(k0 + row) * ldb + c16 * 4);
        }
    };

    float acc[4][8][4];
#pragma unroll
    for (int i = 0; i < 4; i++)
#pragma unroll
        for (int j = 0; j < 8; j++)
#pragma unroll
            for (int r = 0; r < 4; r++) acc[i][j][r] = 0.f;

    load_stage(0, 0); CP_COMMIT();
    load_stage(1, 1); CP_COMMIT();

    for (int i = 0; i < T; i++) {
        if (i + 2 < T) load_stage(i + 2, (i + 2) % NSTAGE);
        CP_COMMIT();
        CP_WAIT(2);
        __syncthreads();

        const float* As = (const float*)(smem + (size_t)(i % NSTAGE) * STAGE_BYTES);
        const float* Bs = (const float*)((const char*)As + A_BYTES);

#pragma unroll
        for (int k8 = 0; k8 < BK / 8; k8++) {
            const int kk = k8 * 8;
            float a[4][4], b[8][2];
#pragma unroll
            for (int mi = 0; mi < 4; mi++) {
                const int am = wm * 64 + mi * 16 + lr;
                a[mi][0] = As[(size_t)am * A_STRIDE + kk + lc];
                a[mi][1] = As[(size_t)(am + 8) * A_STRIDE + kk + lc];
                a[mi][2] = As[(size_t)am * A_STRIDE + kk + 4 + lc];
                a[mi][3] = As[(size_t)(am + 8) * A_STRIDE + kk + 4 + lc];
            }
#pragma unroll
            for (int ni = 0; ni < 8; ni++) {
                const int bn = wn * 64 + ni * 8 + lr;
                b[ni][0] = Bs[(size_t)(kk + lc) * B_STRIDE + bn];
                b[ni][1] = Bs[(size_t)(kk + 4 + lc) * B_STRIDE + bn];
            }
#pragma unroll
            for (int mi = 0; mi < 4; mi++)
#pragma unroll
                for (int ni = 0; ni < 8; ni++)
                    mma_tf32(acc[mi][ni], a[mi], b[ni]);
        }
        __syncthreads();
    }

    // Epilogue: c0,c1 -> (row, col..col+1); c2,c3 -> (row+8, ...)
#pragma unroll
    for (int mi = 0; mi < 4; mi++) {
#pragma unroll
        for (int half = 0; half < 2; half++) {
            const size_t row = (size_t)m0 + wm * 64 + mi * 16 + lr + half * 8;
#pragma unroll
            for (int ni = 0; ni < 8; ni++) {
                const int col = n0 + wn * 64 + ni * 8 + lc * 2;
                float x = acc[mi][ni][half * 2 + 0];
                float y = acc[mi][ni][half * 2 + 1];
                if (MODE == 0) {
                    *(float2*)(C0 + row * ldc + col) = make_float2(x, y);
                    *(float2*)(C1 + row * ldc + col) =
                        make_float2(fmaxf(x, 0.f), fmaxf(y, 0.f));
                } else {
                    *(float2*)(C0 + row * ldc + col) =
                        make_float2(fmaxf(x, 0.f), fmaxf(y, 0.f));
                }
            }
        }
    }
}

// ---------------------------------------------------------------------------
// BN stats: 2D grid (48 col-blocks x 16 row-chunks), atomics into g_bnsum/sq.
// ---------------------------------------------------------------------------
__global__ void bn_stats_kernel(const float* __restrict__ agg,
                                const float* __restrict__ gen)
{
    const int c0 = blockIdx.x * 32;
    const int cx = threadIdx.x & 31;
    const int ry = threadIdx.x >> 5;   // 0..7
    const int c  = c0 + cx;

    const float* base;
    int stride;
    if (c0 < FEAT) { base = agg + c;          stride = FEAT; }
    else           { base = gen + (c - FEAT); stride = F2;   }

    const int r0 = blockIdx.y * 512;
    float sum = 0.f, sq = 0.f;
#pragma unroll 8
    for (int r = r0 + ry; r < r0 + 512; r += 8) {
        float v = base[(size_t)r * stride];
        sum += v; sq += v * v;
    }
    __shared__ float ssum[8][32], ssq[8][32];
    ssum[ry][cx] = sum; ssq[ry][cx] = sq;
    __syncthreads();
    if (ry == 0) {
#pragma unroll
        for (int r = 1; r < 8; r++) { sum += ssum[r][cx]; sq += ssq[r][cx]; }
        atomicAdd(&g_bnsum[c], sum);
        atomicAdd(&g_bnsq[c], sq);
    }
}

__global__ void bn_finalize(const float* __restrict__ gamma,
                            const float* __restrict__ beta)
{
    int c = blockIdx.x * blockDim.x + threadIdx.x;
    if (c >= F3) return;
    const float inv = 1.0f / (float)BATCH;
    float mean = g_bnsum[c] * inv;
    float var  = g_bnsq[c] * inv - mean * mean;
    float s = gamma[c] * rsqrtf(var + BN_EPS);
    g_s[c] = s;
    g_t[c] = beta[c] - mean * s;
}

// ---------------------------------------------------------------------------
// xhat = round_tf32(feats * s + t)
// ---------------------------------------------------------------------------
__global__ void xhat_kernel(const float* __restrict__ agg,
                            const float* __restrict__ gen)
{
    size_t t = (size_t)blockIdx.x * blockDim.x + threadIdx.x;
    int m = (int)(t / (F3 / 4));
    int c = (int)(t % (F3 / 4)) * 4;

    float4 v;
    if (c < FEAT) v = *(const float4*)(agg + (size_t)m * FEAT + c);
    else          v = *(const float4*)(gen + (size_t)m * F2 + (c - FEAT));
    float4 s4 = *(const float4*)(g_s + c);
    float4 t4 = *(const float4*)(g_t + c);
    float4 o = make_float4(v.x * s4.x + t4.x, v.y * s4.y + t4.y,
                           v.z * s4.z + t4.z, v.w * s4.w + t4.w);
    *(float4*)(g_xhat + (size_t)m * F3 + c) = tf32r4(o);
}

// ---------------------------------------------------------------------------
extern "C" void kernel_launch(void* const* d_in, const int* in_sizes, int n_in,
                              void* d_out, int out_size)
{
    const float* feat  = (const float*)d_in[0];
    const float* Wg    = (const float*)d_in[1];
    const float* W1    = (const float*)d_in[2];
    const float* gamma = (const float*)d_in[3];
    const float* beta  = (const float*)d_in[4];
    const int*   neigh = (const int*)d_in[6];

    float* out   = (float*)d_out;
    float* aggO  = out + OFF_AGG;
    float* toO   = out + OFF_TO;
    float* genO  = out + OFF_GEN;
    float* rawO  = out + OFF_RAW;
    float* egenO = out + OFF_EGEN;
    float* erawO = out + OFF_ERAW;

    float *p_cat, *p_env, *p_xhat, *p_Wg2, *p_W12, *p_sum, *p_sq;
    cudaGetSymbolAddress((void**)&p_cat,  g_cat);
    cudaGetSymbolAddress((void**)&p_env,  g_env);
    cudaGetSymbolAddress((void**)&p_xhat, g_xhat);
    cudaGetSymbolAddress((void**)&p_Wg2,  g_Wg2);
    cudaGetSymbolAddress((void**)&p_W12,  g_W12);
    cudaGetSymbolAddress((void**)&p_sum,  g_bnsum);
    cudaGetSymbolAddress((void**)&p_sq,   g_bnsq);

    const int smem_bytes = NSTAGE * STAGE_BYTES;   // 156672
    cudaFuncSetAttribute(mma_gemm<0>, cudaFuncAttributeMaxDynamicSharedMemorySize, smem_bytes);
    cudaFuncSetAttribute(mma_gemm<1>, cudaFuncAttributeMaxDynamicSharedMemorySize, smem_bytes);

    // 0) weight tf32 round-copies + BN accumulator reset
    round_copy<<<(unsigned)((size_t)F2 * F2 / 4 / 256), 256>>>(Wg, p_Wg2, (size_t)F2 * F2 / 4);
    round_copy<<<(unsigned)((size_t)F3 * F3 / 4 / 256), 256>>>(W1, p_W12, (size_t)F3 * F3 / 4);
    cudaMemsetAsync(p_sum, 0, F3 * sizeof(float));
    cudaMemsetAsync(p_sq,  0, F3 * sizeof(float));

    // 1) gather + pooling (+tf32-rounded staging)
    gather_kernel<<<BATCH, 128>>>(feat, neigh, aggO);

    // 2) raw/gen = cat @ W_gen          [8192,1024] x [1024,1024]
    mma_gemm<0><<<dim3(F2/BN, BATCH/BM), 256, smem_bytes>>>(
        p_cat, p_Wg2, rawO, genO, F2, F2, F2, F2);

    // 3) env_raw/env_gen = env @ W_gen[512:,:]   [8192,512] x [512,1024]
    mma_gemm<0><<<dim3(F2/BN, BATCH/BM), 256, smem_bytes>>>(
        p_env, p_Wg2 + (size_t)FEAT * F2, erawO, egenO, FEAT, FEAT, F2, F2);

    // 4) BN statistics + finalize
    bn_stats_kernel<<<dim3(F3/32, 16), 256>>>(aggO, genO);
    bn_finalize<<<F3/256, 256>>>(gamma, beta);

    // 5) xhat = feats*s + t (tf32-rounded)
    xhat_kernel<<<(unsigned)((size_t)BATCH * F3 / 4 / 256), 256>>>(aggO, genO);

    // 6) to_feats = relu(xhat @ weight1)   [8192,1536] x [1536,1536]
    mma_gemm<1><<<dim3(F3/BN, BATCH/BM), 256, smem_bytes>>>(
        p_xhat, p_W12, toO, nullptr, F3, F3, F3, F3);

    (void)in_sizes; (void)n_in; (void)out_size;
}

// round 7
// speedup vs baseline: 3.0342x; 1.0031x over previous
#include <cuda_runtime.h>
#include <cuda_bf16.h>
#include <cstdint>

// Problem constants
#define BATCH 8192
#define FEAT  512
#define DEG   32
#define F2    1024   // 2*FEAT
#define F3    1536   // 3*FEAT
#define BN_EPS 1e-5f

// Output layout (floats): agg, to_feats, gen, raw, env_gen, env_raw
#define OFF_AGG   0
#define OFF_TO    (BATCH*FEAT)
#define OFF_GEN   (OFF_TO   + BATCH*F3)
#define OFF_RAW   (OFF_GEN  + BATCH*F2)
#define OFF_EGEN  (OFF_RAW  + BATCH*F2)
#define OFF_ERAW  (OFF_EGEN + BATCH*F2)

// ---------------- scratch (__device__ globals; no allocations) --------------
__device__ float g_cat [(size_t)BATCH * F2];   // [self | agg] tf32-rounded
__device__ float g_env [(size_t)BATCH * FEAT]; // env_agg tf32-rounded
__device__ float g_genr[(size_t)BATCH * F2];   // tf32-rounded relu(raw) = gen
__device__ float g_Wg2 [(size_t)F2 * F2];      // W_gen tf32-rounded, [K][N]
__device__ float g_W1s [(size_t)F3 * F3];      // round(s_k * W1[k][n]), [K][N]
__device__ float g_s[F3];
__device__ float g_t[F3];
__device__ float g_bias[F3];                   // t @ W1
__device__ float g_bnsum[F3];
__device__ float g_bnsq[F3];

// ------------------------------- helpers ------------------------------------
__device__ __forceinline__ float tf32r(float v) {
    uint32_t u;
    asm("cvt.rna.tf32.f32 %0, %1;" : "=r"(u) : "f"(v));
    return __uint_as_float(u);
}
__device__ __forceinline__ float4 tf32r4(float4 v) {
    return make_float4(tf32r(v.x), tf32r(v.y), tf32r(v.z), tf32r(v.w));
}
__device__ __forceinline__ uint32_t smem_u32(const void* p) {
    uint32_t a;
    asm("{ .reg .u64 t; cvta.to.shared.u64 t, %1; cvt.u32.u64 %0, t; }"
        : "=r"(a) : "l"(p));
    return a;
}
__device__ __forceinline__ void cp_async16(uint32_t dst, const void* src) {
    asm volatile("cp.async.cg.shared.global [%0], [%1], 16;" :: "r"(dst), "l"(src));
}
#define CP_COMMIT() asm volatile("cp.async.commit_group;" ::: "memory")
#define CP_WAIT(n)  asm volatile("cp.async.wait_group %0;" :: "n"(n) : "memory")

__device__ __forceinline__ void mma_tf32(float* c, const float* a, const float* b) {
    asm volatile(
        "mma.sync.aligned.m16n8k8.row.col.f32.tf32.tf32.f32 "
        "{%0,%1,%2,%3}, {%4,%5,%6,%7}, {%8,%9}, {%0,%1,%2,%3};"
        : "+f"(c[0]), "+f"(c[1]), "+f"(c[2]), "+f"(c[3])
        : "r"(__float_as_uint(a[0])), "r"(__float_as_uint(a[1])),
          "r"(__float_as_uint(a[2])), "r"(__float_as_uint(a[3])),
          "r"(__float_as_uint(b[0])), "r"(__float_as_uint(b[1])));
}

// ---------------------------------------------------------------------------
// Gather + mean-pool (also writes tf32-rounded staging for GEMMs).
// ---------------------------------------------------------------------------
__global__ void gather_kernel(const float* __restrict__ feat,
                              const int*  __restrict__ neigh,
                              float* __restrict__ aggO)
{
    const int m = blockIdx.x;
    __shared__ int idx[DEG];
    if (threadIdx.x < DEG) idx[threadIdx.x] = neigh[(size_t)m * DEG + threadIdx.x];
    __syncthreads();

    const int c = threadIdx.x * 4;

    float4 v0 = *(const float4*)(feat + (size_t)idx[0] * FEAT + c);
    float sx = v0.x, sy = v0.y, sz = v0.z, sw = v0.w;
#pragma unroll 8
    for (int j = 1; j < DEG; j++) {
        float4 v = *(const float4*)(feat + (size_t)idx[j] * FEAT + c);
        sx += v.x; sy += v.y; sz += v.z; sw += v.w;
    }
    const float r32 = 1.0f / 32.0f;
    const float r31 = 1.0f / 31.0f;
    float4 agg = make_float4(sx * r32, sy * r32, sz * r32, sw * r32);
    float4 env = make_float4((sx - v0.x) * r31, (sy - v0.y) * r31,
                             (sz - v0.z) * r31, (sw - v0.w) * r31);

    *(float4*)(g_cat + (size_t)m * F2 + c)        = tf32r4(v0);
    *(float4*)(g_cat + (size_t)m * F2 + FEAT + c) = tf32r4(agg);
    *(float4*)(aggO  + (size_t)m * FEAT + c)      = agg;     // exact output
    *(float4*)(g_env + (size_t)m * FEAT + c)      = tf32r4(env);
}

// ---------------------------------------------------------------------------
// Elementwise tf32 round-copy.
// ---------------------------------------------------------------------------
__global__ void round_copy(const float* __restrict__ src, float* __restrict__ dst,
                           size_t n4)
{
    size_t i = (size_t)blockIdx.x * blockDim.x + threadIdx.x;
    if (i < n4) ((float4*)dst)[i] = tf32r4(((const float4*)src)[i]);
}

// W1s[k][n] = round(s[k] * W1[k][n])
__global__ void w1_scale(const float* __restrict__ W1, float* __restrict__ dst)
{
    size_t i = (size_t)blockIdx.x * blockDim.x + threadIdx.x;  // float4 units
    int k = (int)(i / (F3 / 4));
    float s = g_s[k];
    float4 v = ((const float4*)W1)[i];
    ((float4*)dst)[i] = tf32r4(make_float4(v.x * s, v.y * s, v.z * s, v.w * s));
}

// bias[n] = sum_k t[k] * W1[k][n].  One block per 32 n-cols, 8 k-lanes.
__global__ void bias_kernel(const float* __restrict__ W1)
{
    const int n = blockIdx.x * 32 + (threadIdx.x & 31);
    const int kl = threadIdx.x >> 5;   // 0..7
    float sum = 0.f;
    for (int k = kl; k < F3; k += 8)
        sum += g_t[k] * W1[(size_t)k * F3 + n];
    __shared__ float red[8][32];
    red[kl][threadIdx.x & 31] = sum;
    __syncthreads();
    if (kl == 0) {
#pragma unroll
        for (int r = 1; r < 8; r++) sum += red[r][threadIdx.x & 31];
        g_bias[n] = sum;
    }
}

// ---------------------------------------------------------------------------
// tf32 mma.sync GEMM: block 128x256x32, 8 warps (2x4), warp 64x64.
// 4-stage cp.async pipeline, 1 sync/iter, register-double-buffered fragments.
// A operand split across two sources at k == splitK (for fused GEMM3).
// MODE 0: C0=raw, C1=relu.   MODE 2: C0=raw, C1=relu, C2=round(relu).
// MODE 1: C0 = relu(acc + bias[col]).
// ---------------------------------------------------------------------------
#define BM 128
#define BN 256
#define BK 32
#define NSTAGE 4
#define A_STRIDE 36
#define B_STRIDE 264
#define A_BYTES (BM * A_STRIDE * 4)                 // 18432
#define STAGE_BYTES (A_BYTES + BK * B_STRIDE * 4)   // 52224

template <int MODE>
__global__ void __launch_bounds__(256)
mma_gemm(const float* __restrict__ A, const float* __restrict__ A2,
         const float* __restrict__ B,
         float* __restrict__ C0, float* __restrict__ C1, float* __restrict__ C2,
         const float* __restrict__ bias,
         int K, int splitK, int lda, int lda2, int ldb, int ldc)
{
    extern __shared__ __align__(16) char smem[];
    const uint32_t sbase = smem_u32(smem);
    const int tid = threadIdx.x, wid = tid >> 5, lane = tid & 31;
    const int wm = wid >> 2, wn = wid & 3;       // warp grid 2 x 4
    const int lr = lane >> 2, lc = lane & 3;
    const int m0 = blockIdx.y * BM, n0 = blockIdx.x * BN;
    const int T = K / BK;

    const float* Bp = B + n0;

    auto load_stage = [&](int blk, int s) {
        const uint32_t a_s = sbase + (uint32_t)s * STAGE_BYTES;
        const uint32_t b_s = a_s + A_BYTES;
        const int k0 = blk * BK;
        const float* Ap;
        int ld;
        if (k0 < splitK) { Ap = A + (size_t)m0 * lda + k0;          ld = lda;  }
        else             { Ap = A2 + (size_t)m0 * lda2 + (k0 - splitK); ld = lda2; }
#pragma unroll
        for (int u = 0; u < 4; u++) {            // A: 1024 16B chunks
            int ch = tid + u * 256;
            int row = ch >> 3, c16 = ch & 7;
            cp_async16(a_s + (uint32_t)row * (A_STRIDE * 4) + c16 * 16,
                       Ap + (size_t)row * ld + c16 * 4);
        }
#pragma unroll
        for (int u = 0; u < 8; u++) {            // B: 2048 16B chunks
            int ch = tid + u * 256;
            int row = ch >> 6, c16 = ch & 63;
            cp_async16(b_s + (uint32_t)row * (B_STRIDE * 4) + c16 * 16,
                       Bp + (size_t)(k0 + row) * ldb + c16 * 4);
        }
    };

    // fragment loader: stage s, k8 sub-step
    auto load_frags = [&](int s, int k8, float a[4][4], float b[8][2]) {
        const float* As = (const float*)(smem + (size_t)s * STAGE_BYTES);
        const float* Bs = (const float*)((const char*)As + A_BYTES);
        const int kk = k8 * 8;
#pragma unroll
        for (int mi = 0; mi < 4; mi++) {
            const int am = wm * 64 + mi * 16 + lr;
            a[mi][0] = As[(size_t)am * A_STRIDE + kk + lc];
            a[mi][1] = As[(size_t)(am + 8) * A_STRIDE + kk + lc];
            a[mi][2] = As[(size_t)am * A_STRIDE + kk + 4 + lc];
            a[mi][3] = As[(size_t)(am + 8) * A_STRIDE + kk + 4 + lc];
        }
#pragma unroll
        for (int ni = 0; ni < 8; ni++) {
            const int bn = wn * 64 + ni * 8 + lr;
            b[ni][0] = Bs[(size_t)(kk + lc) * B_STRIDE + bn];
            b[ni][1] = Bs[(size_t)(kk + 4 + lc) * B_STRIDE + bn];
        }
    };

    float acc[4][8][4];
#pragma unroll
    for (int i = 0; i < 4; i++)
#pragma unroll
        for (int j = 0; j < 8; j++)
#pragma unroll
            for (int r = 0; r < 4; r++) acc[i][j][r] = 0.f;

    load_stage(0, 0); CP_COMMIT();
    load_stage(1, 1); CP_COMMIT();
    load_stage(2, 2); CP_COMMIT();

    CP_WAIT(2);               // stage 0 complete (3 committed, <=2 outstanding)
    __syncthreads();          // stage 0 visible to all warps

    float a_cur[4][4], b_cur[8][2], a_nxt[4][4], b_nxt[8][2];
    load_frags(0, 0, a_cur, b_cur);

    for (int i = 0; i < T; i++) {
        // committed so far: min(i+3, T) stages. After wait(1): stages <= i+1 done.
        CP_WAIT(1);
        __syncthreads();      // all warps done computing stage i-1; stage i+1 visible
        if (i + 3 < T) load_stage(i + 3, (i + 3) & 3);
        CP_COMMIT();

#pragma unroll
        for (int k8 = 0; k8 < BK / 8; k8++) {
            // prefetch next fragments (next k8, or k8=0 of next stage)
            if (k8 < 3) {
                load_frags(i & 3, k8 + 1, a_nxt, b_nxt);
            } else if (i + 1 < T) {
                load_frags((i + 1) & 3, 0, a_nxt, b_nxt);
            }
#pragma unroll
            for (int mi = 0; mi < 4; mi++)
#pragma unroll
                for (int ni = 0; ni < 8; ni++)
                    mma_tf32(acc[mi][ni], a_cur[mi], b_nxt == nullptr ? b_cur[ni] : b_cur[ni]);
            // swap cur <-> nxt
#pragma unroll
            for (int mi = 0; mi < 4; mi++)
#pragma unroll
                for (int r = 0; r < 4; r++) a_cur[mi][r] = a_nxt[mi][r];
#pragma unroll
            for (int ni = 0; ni < 8; ni++) {
                b_cur[ni][0] = b_nxt[ni][0];
                b_cur[ni][1] = b_nxt[ni][1];
            }
        }
    }

    // Epilogue
#pragma unroll
    for (int mi = 0; mi < 4; mi++) {
#pragma unroll
        for (int half = 0; half < 2; half++) {
            const size_t row = (size_t)m0 + wm * 64 + mi * 16 + lr + half * 8;
#pragma unroll
            for (int ni = 0; ni < 8; ni++) {
                const int col = n0 + wn * 64 + ni * 8 + lc * 2;
                float x = acc[mi][ni][half * 2 + 0];
                float y = acc[mi][ni][half * 2 + 1];
                if (MODE == 1) {
                    x = fmaxf(x + bias[col], 0.f);
                    y = fmaxf(y + bias[col + 1], 0.f);
                    *(float2*)(C0 + row * ldc + col) = make_float2(x, y);
                } else {
                    *(float2*)(C0 + row * ldc + col) = make_float2(x, y);
                    float rx = fmaxf(x, 0.f), ry = fmaxf(y, 0.f);
                    *(float2*)(C1 + row * ldc + col) = make_float2(rx, ry);
                    if (MODE == 2)
                        *(float2*)(C2 + row * ldc + col) =
                            make_float2(tf32r(rx), tf32r(ry));
                }
            }
        }
    }
}

// ---------------------------------------------------------------------------
// BN stats: 2D grid (48 col-blocks x 16 row-chunks), atomics into g_bnsum/sq.
// ---------------------------------------------------------------------------
__global__ void bn_stats_kernel(const float* __restrict__ agg,
                                const float* __restrict__ gen)
{
    const int c0 = blockIdx.x * 32;
    const int cx = threadIdx.x & 31;
    const int ry = threadIdx.x >> 5;   // 0..7
    const int c  = c0 + cx;

    const float* base;
    int stride;
    if (c0 < FEAT) { base = agg + c;          stride = FEAT; }
    else           { base = gen + (c - FEAT); stride = F2;   }

    const int r0 = blockIdx.y * 512;
    float sum = 0.f, sq = 0.f;
#pragma unroll 8
    for (int r = r0 + ry; r < r0 + 512; r += 8) {
        float v = base[(size_t)r * stride];
        sum += v; sq += v * v;
    }
    __shared__ float ssum[8][32], ssq[8][32];
    ssum[ry][cx] = sum; ssq[ry][cx] = sq;
    __syncthreads();
    if (ry == 0) {
#pragma unroll
        for (int r = 1; r < 8; r++) { sum += ssum[r][cx]; sq += ssq[r][cx]; }
        atomicAdd(&g_bnsum[c], sum);
        atomicAdd(&g_bnsq[c], sq);
    }
}

__global__ void bn_finalize(const float* __restrict__ gamma,
                            const float* __restrict__ beta)
{
    int c = blockIdx.x * blockDim.x + threadIdx.x;
    if (c >= F3) return;
    const float inv = 1.0f / (float)BATCH;
    float mean = g_bnsum[c] * inv;
    float var  = g_bnsq[c] * inv - mean * mean;
    float s = gamma[c] * rsqrtf(var + BN_EPS);
    g_s[c] = s;
    g_t[c] = beta[c] - mean * s;
}

// ---------------------------------------------------------------------------
extern "C" void kernel_launch(void* const* d_in, const int* in_sizes, int n_in,
                              void* d_out, int out_size)
{
    const float* feat  = (const float*)d_in[0];
    const float* Wg    = (const float*)d_in[1];
    const float* W1    = (const float*)d_in[2];
    const float* gamma = (const float*)d_in[3];
    const float* beta  = (const float*)d_in[4];
    const int*   neigh = (const int*)d_in[6];

    float* out   = (float*)d_out;
    float* aggO  = out + OFF_AGG;
    float* toO   = out + OFF_TO;
    float* genO  = out + OFF_GEN;
    float* rawO  = out + OFF_RAW;
    float* egenO = out + OFF_EGEN;
    float* erawO = out + OFF_ERAW;

    float *p_cat, *p_env, *p_genr, *p_Wg2, *p_W1s, *p_sum, *p_sq, *p_bias;
    cudaGetSymbolAddress((void**)&p_cat,  g_cat);
    cudaGetSymbolAddress((void**)&p_env,  g_env);
    cudaGetSymbolAddress((void**)&p_genr, g_genr);
    cudaGetSymbolAddress((void**)&p_Wg2,  g_Wg2);
    cudaGetSymbolAddress((void**)&p_W1s,  g_W1s);
    cudaGetSymbolAddress((void**)&p_sum,  g_bnsum);
    cudaGetSymbolAddress((void**)&p_sq,   g_bnsq);
    cudaGetSymbolAddress((void**)&p_bias, g_bias);

    const int smem_bytes = NSTAGE * STAGE_BYTES;   // 208896
    cudaFuncSetAttribute(mma_gemm<0>, cudaFuncAttributeMaxDynamicSharedMemorySize, smem_bytes);
    cudaFuncSetAttribute(mma_gemm<1>, cudaFuncAttributeMaxDynamicSharedMemorySize, smem_bytes);
    cudaFuncSetAttribute(mma_gemm<2>, cudaFuncAttributeMaxDynamicSharedMemorySize, smem_bytes);

    // 0) W_gen tf32 round-copy + BN accumulator reset
    round_copy<<<(unsigned)((size_t)F2 * F2 / 4 / 256), 256>>>(Wg, p_Wg2, (size_t)F2 * F2 / 4);
    cudaMemsetAsync(p_sum, 0, F3 * sizeof(float));
    cudaMemsetAsync(p_sq,  0, F3 * sizeof(float));

    // 1) gather + pooling (+tf32-rounded staging)
    gather_kernel<<<BATCH, 128>>>(feat, neigh, aggO);

    // 2) raw/gen = cat @ W_gen  [8192,1024]x[1024,1024]; also writes rounded gen
    mma_gemm<2><<<dim3(F2/BN, BATCH/BM), 256, smem_bytes>>>(
        p_cat, p_cat, p_Wg2, rawO, genO, p_genr, nullptr,
        F2, F2, F2, F2, F2, F2);

    // 3) env_raw/env_gen = env @ W_gen[512:,:]   [8192,512]x[512,1024]
    mma_gemm<0><<<dim3(F2/BN, BATCH/BM), 256, smem_bytes>>>(
        p_env, p_env, p_Wg2 + (size_t)FEAT * F2, erawO, egenO, nullptr, nullptr,
        FEAT, FEAT, FEAT, FEAT, F2, F2);

    // 4) BN statistics + finalize
    bn_stats_kernel<<<dim3(F3/32, 16), 256>>>(aggO, genO);
    bn_finalize<<<F3/256, 256>>>(gamma, beta);

    // 5) fold BN into GEMM3: W1s = round(diag(s) @ W1), bias = t @ W1
    w1_scale<<<(unsigned)((size_t)F3 * F3 / 4 / 256), 256>>>(W1, p_W1s);
    bias_kernel<<<F3/32, 256>>>(W1);

    // 6) to_feats = relu([agg|gen]_r @ W1s + bias)   [8192,1536]x[1536,1536]
    //    A: k<512 from g_cat agg half (rounded), k>=512 from g_genr (rounded)
    mma_gemm<1><<<dim3(F3/BN, BATCH/BM), 256, smem_bytes>>>(
        p_cat + FEAT, p_genr, p_W1s, toO, nullptr, nullptr, p_bias,
        F3, FEAT, F2, F2, F3, F3);

    (void)in_sizes; (void)n_in; (void)out_size;
}

// round 8
// speedup vs baseline: 3.0499x; 1.0052x over previous
#include <cuda_runtime.h>
#include <cuda_bf16.h>
#include <cstdint>

// Problem constants
#define BATCH 8192
#define FEAT  512
#define DEG   32
#define F2    1024   // 2*FEAT
#define F3    1536   // 3*FEAT
#define BN_EPS 1e-5f

// Output layout (floats): agg, to_feats, gen, raw, env_gen, env_raw
#define OFF_AGG   0
#define OFF_TO    (BATCH*FEAT)
#define OFF_GEN   (OFF_TO   + BATCH*F3)
#define OFF_RAW   (OFF_GEN  + BATCH*F2)
#define OFF_EGEN  (OFF_RAW  + BATCH*F2)
#define OFF_ERAW  (OFF_EGEN + BATCH*F2)

// ---------------- scratch (__device__ globals; no allocations) --------------
__device__ float g_cat [(size_t)BATCH * F2];   // [self | agg] tf32-rounded
__device__ float g_env [(size_t)BATCH * FEAT]; // env_agg tf32-rounded
__device__ float g_genr[(size_t)BATCH * F2];   // tf32-rounded relu(raw) = gen
__device__ float g_WgT [(size_t)F2 * F2];      // W_gen^T rounded, [N][K] K-major
__device__ float g_W1sT[(size_t)F3 * F3];      // round(s_k*W1[k][n])^T, [N][K]
__device__ float g_s[F3];
__device__ float g_t[F3];
__device__ float g_bias[F3];                   // t @ W1
__device__ float g_bnsum[F3];
__device__ float g_bnsq[F3];

// ------------------------------- helpers ------------------------------------
__device__ __forceinline__ float tf32r(float v) {
    uint32_t u;
    asm("cvt.rna.tf32.f32 %0, %1;" : "=r"(u) : "f"(v));
    return __uint_as_float(u);
}
__device__ __forceinline__ float4 tf32r4(float4 v) {
    return make_float4(tf32r(v.x), tf32r(v.y), tf32r(v.z), tf32r(v.w));
}
__device__ __forceinline__ uint32_t smem_u32(const void* p) {
    uint32_t a;
    asm("{ .reg .u64 t; cvta.to.shared.u64 t, %1; cvt.u32.u64 %0, t; }"
        : "=r"(a) : "l"(p));
    return a;
}
__device__ __forceinline__ void cp_async16(uint32_t dst, const void* src) {
    asm volatile("cp.async.cg.shared.global [%0], [%1], 16;" :: "r"(dst), "l"(src));
}
#define CP_COMMIT() asm volatile("cp.async.commit_group;" ::: "memory")
#define CP_WAIT(n)  asm volatile("cp.async.wait_group %0;" :: "n"(n) : "memory")

__device__ __forceinline__ void ldsm4(uint32_t& r0, uint32_t& r1, uint32_t& r2,
                                      uint32_t& r3, uint32_t addr) {
    asm volatile("ldmatrix.sync.aligned.m8n8.x4.shared.b16 {%0,%1,%2,%3}, [%4];"
                 : "=r"(r0), "=r"(r1), "=r"(r2), "=r"(r3) : "r"(addr));
}
__device__ __forceinline__ void mma_tf32(float* c, const uint32_t* a, const uint32_t* b) {
    asm volatile(
        "mma.sync.aligned.m16n8k8.row.col.f32.tf32.tf32.f32 "
        "{%0,%1,%2,%3}, {%4,%5,%6,%7}, {%8,%9}, {%0,%1,%2,%3};"
        : "+f"(c[0]), "+f"(c[1]), "+f"(c[2]), "+f"(c[3])
        : "r"(a[0]), "r"(a[1]), "r"(a[2]), "r"(a[3]), "r"(b[0]), "r"(b[1]));
}

// ---------------------------------------------------------------------------
// Gather + mean-pool (also writes tf32-rounded staging for GEMMs).
// ---------------------------------------------------------------------------
__global__ void gather_kernel(const float* __restrict__ feat,
                              const int*  __restrict__ neigh,
                              float* __restrict__ aggO)
{
    const int m = blockIdx.x;
    __shared__ int idx[DEG];
    if (threadIdx.x < DEG) idx[threadIdx.x] = neigh[(size_t)m * DEG + threadIdx.x];
    __syncthreads();

    const int c = threadIdx.x * 4;

    float4 v0 = *(const float4*)(feat + (size_t)idx[0] * FEAT + c);
    float sx = v0.x, sy = v0.y, sz = v0.z, sw = v0.w;
#pragma unroll 8
    for (int j = 1; j < DEG; j++) {
        float4 v = *(const float4*)(feat + (size_t)idx[j] * FEAT + c);
        sx += v.x; sy += v.y; sz += v.z; sw += v.w;
    }
    const float r32 = 1.0f / 32.0f;
    const float r31 = 1.0f / 31.0f;
    float4 agg = make_float4(sx * r32, sy * r32, sz * r32, sw * r32);
    float4 env = make_float4((sx - v0.x) * r31, (sy - v0.y) * r31,
                             (sz - v0.z) * r31, (sw - v0.w) * r31);

    *(float4*)(g_cat + (size_t)m * F2 + c)        = tf32r4(v0);
    *(float4*)(g_cat + (size_t)m * F2 + FEAT + c) = tf32r4(agg);
    *(float4*)(aggO  + (size_t)m * FEAT + c)      = agg;     // exact output
    *(float4*)(g_env + (size_t)m * FEAT + c)      = tf32r4(env);
}

// ---------------------------------------------------------------------------
// Transpose + tf32 round (+ optional per-source-row scale by g_s):
// dst[c][r] = round(scale(r) * src[r][c]);  src [R][C], dst [C][R].
// ---------------------------------------------------------------------------
template <bool SCALE>
__global__ void transpose_round(const float* __restrict__ src,
                                float* __restrict__ dst, int R, int C)
{
    __shared__ float t[32][33];
    const int bx = blockIdx.x * 32, by = blockIdx.y * 32;
#pragma unroll
    for (int j = 0; j < 32; j += 8)
        t[threadIdx.y + j][threadIdx.x] =
            src[(size_t)(by + threadIdx.y + j) * C + bx + threadIdx.x];
    __syncthreads();
    const float sc = SCALE ? g_s[by + threadIdx.x] : 1.0f;
#pragma unroll
    for (int j = 0; j < 32; j += 8) {
        float v = t[threadIdx.x][threadIdx.y + j];
        if (SCALE) v *= sc;
        dst[(size_t)(bx + threadIdx.y + j) * R + by + threadIdx.x] = tf32r(v);
    }
}

// bias[n] = sum_k t[k] * W1[k][n].  One block per 32 n-cols, 8 k-lanes.
__global__ void bias_kernel(const float* __restrict__ W1)
{
    const int n = blockIdx.x * 32 + (threadIdx.x & 31);
    const int kl = threadIdx.x >> 5;   // 0..7
    float sum = 0.f;
    for (int k = kl; k < F3; k += 8)
        sum += g_t[k] * W1[(size_t)k * F3 + n];
    __shared__ float red[8][32];
    red[kl][threadIdx.x & 31] = sum;
    __syncthreads();
    if (kl == 0) {
#pragma unroll
        for (int r = 1; r < 8; r++) sum += red[r][threadIdx.x & 31];
        g_bias[n] = sum;
    }
}

// ---------------------------------------------------------------------------
// tf32 mma.sync GEMM with ldmatrix operand loads.
// Block 128x256x32, 8 warps (2x4), warp 64x64. 4-stage cp.async pipeline.
// A [M][K] row-major; BT [N][K] row-major (K-major weights). Both tf32-rounded.
// SMEM per stage: As[128][36], Bs[256][36] (rows = 144B, LDSM conflict-free).
// MODE 0: C0=raw, C1=relu.  MODE 2: + C2=round(relu).  MODE 1: C0=relu(acc+bias).
// ---------------------------------------------------------------------------
#define BM 128
#define BN 256
#define BK 32
#define NSTAGE 4
#define OP_STRIDE 144                              // 36 floats per row
#define A_BYTES (BM * OP_STRIDE)                   // 18432
#define B_BYTES (BN * OP_STRIDE)                   // 36864
#define STAGE_BYTES (A_BYTES + B_BYTES)            // 55296

template <int MODE>
__global__ void __launch_bounds__(256)
mma_gemm(const float* __restrict__ A, const float* __restrict__ A2,
         const float* __restrict__ BT,
         float* __restrict__ C0, float* __restrict__ C1, float* __restrict__ C2,
         const float* __restrict__ bias,
         int K, int splitK, int lda, int lda2, int ldb, int ldc)
{
    extern __shared__ __align__(16) char smem[];
    const uint32_t sbase = smem_u32(smem);
    const int tid = threadIdx.x, wid = tid >> 5, lane = tid & 31;
    const int wm = wid >> 2, wn = wid & 3;       // warp grid 2 x 4
    const int lr = lane >> 2, lc = lane & 3;
    const int m0 = blockIdx.y * BM, n0 = blockIdx.x * BN;
    const int T = K / BK;

    const float* Bp = BT + (size_t)n0 * ldb;

    auto load_stage = [&](int blk, int s) {
        const uint32_t a_s = sbase + (uint32_t)s * STAGE_BYTES;
        const uint32_t b_s = a_s + A_BYTES;
        const int k0 = blk * BK;
        const float* Ap;
        int ld;
        if (k0 < splitK) { Ap = A + (size_t)m0 * lda + k0;             ld = lda;  }
        else             { Ap = A2 + (size_t)m0 * lda2 + (k0 - splitK); ld = lda2; }
#pragma unroll
        for (int u = 0; u < 4; u++) {            // A: 1024 16B chunks
            int ch = tid + u * 256;
            int row = ch >> 3, c16 = ch & 7;
            cp_async16(a_s + (uint32_t)row * OP_STRIDE + c16 * 16,
                       Ap + (size_t)row * ld + c16 * 4);
        }
#pragma unroll
        for (int u = 0; u < 8; u++) {            // B: 2048 16B chunks
            int ch = tid + u * 256;
            int row = ch >> 3, c16 = ch & 7;
            cp_async16(b_s + (uint32_t)row * OP_STRIDE + c16 * 16,
                       Bp + (size_t)row * ldb + k0 + c16 * 4);
        }
    };

    // ldmatrix per-lane base offsets (bytes), stage/k8-invariant part
    //  A: matrices [r0c0, r1c0, r0c1, r1c1] of an m16k8 tile
    const int a_row = wm * 64 + (lane & 15);
    const int a_col = (lane >> 4) * 4;
    const uint32_t aOff = (uint32_t)a_row * OP_STRIDE + a_col * 4;
    //  B: matrices [n0c0, n0c1, n1c0, n1c1] for two n8 blocks
    const int b_row = wn * 64 + (lane & 7) + (lane >> 4) * 8;
    const int b_col = ((lane >> 3) & 1) * 4;
    const uint32_t bOff = (uint32_t)b_row * OP_STRIDE + b_col * 4;

    // load fragments for (stage s, k8): A 4x ldsm4, B 4x ldsm4
    auto load_frags = [&](int s, int k8, uint32_t a[4][4], uint32_t b[4][4]) {
        const uint32_t a_s = sbase + (uint32_t)s * STAGE_BYTES + (uint32_t)k8 * 32;
        const uint32_t b_s = a_s + A_BYTES;
#pragma unroll
        for (int mi = 0; mi < 4; mi++)
            ldsm4(a[mi][0], a[mi][1], a[mi][2], a[mi][3],
                  a_s + aOff + (uint32_t)mi * (16 * OP_STRIDE));
#pragma unroll
        for (int nb = 0; nb < 4; nb++)
            ldsm4(b[nb][0], b[nb][1], b[nb][2], b[nb][3],
                  b_s + bOff + (uint32_t)nb * (16 * OP_STRIDE));
    };

    float acc[4][8][4];
#pragma unroll
    for (int i = 0; i < 4; i++)
#pragma unroll
        for (int j = 0; j < 8; j++)
#pragma unroll
            for (int r = 0; r < 4; r++) acc[i][j][r] = 0.f;

    load_stage(0, 0); CP_COMMIT();
    load_stage(1, 1); CP_COMMIT();
    load_stage(2, 2); CP_COMMIT();

    CP_WAIT(2);               // stage 0 complete
    __syncthreads();

    uint32_t a_cur[4][4], b_cur[4][4], a_nxt[4][4], b_nxt[4][4];
    load_frags(0, 0, a_cur, b_cur);

    for (int i = 0; i < T; i++) {
        CP_WAIT(1);
        __syncthreads();      // stages <= i+1 complete & visible
        if (i + 3 < T) load_stage(i + 3, (i + 3) & 3);
        CP_COMMIT();

#pragma unroll
        for (int k8 = 0; k8 < BK / 8; k8++) {
            if (k8 < 3)           load_frags(i & 3, k8 + 1, a_nxt, b_nxt);
            else if (i + 1 < T)   load_frags((i + 1) & 3, 0, a_nxt, b_nxt);
#pragma unroll
            for (int mi = 0; mi < 4; mi++)
#pragma unroll
                for (int nb = 0; nb < 4; nb++) {
                    mma_tf32(acc[mi][2 * nb + 0], a_cur[mi], &b_cur[nb][0]);
                    mma_tf32(acc[mi][2 * nb + 1], a_cur[mi], &b_cur[nb][2]);
                }
#pragma unroll
            for (int mi = 0; mi < 4; mi++)
#pragma unroll
                for (int r = 0; r < 4; r++) a_cur[mi][r] = a_nxt[mi][r];
#pragma unroll
            for (int nb = 0; nb < 4; nb++)
#pragma unroll
                for (int r = 0; r < 4; r++) b_cur[nb][r] = b_nxt[nb][r];
        }
    }

    // Epilogue
#pragma unroll
    for (int mi = 0; mi < 4; mi++) {
#pragma unroll
        for (int half = 0; half < 2; half++) {
            const size_t row = (size_t)m0 + wm * 64 + mi * 16 + lr + half * 8;
#pragma unroll
            for (int ni = 0; ni < 8; ni++) {
                const int col = n0 + wn * 64 + ni * 8 + lc * 2;
                float x = acc[mi][ni][half * 2 + 0];
                float y = acc[mi][ni][half * 2 + 1];
                if (MODE == 1) {
                    x = fmaxf(x + bias[col], 0.f);
                    y = fmaxf(y + bias[col + 1], 0.f);
                    *(float2*)(C0 + row * ldc + col) = make_float2(x, y);
                } else {
                    *(float2*)(C0 + row * ldc + col) = make_float2(x, y);
                    float rx = fmaxf(x, 0.f), ry = fmaxf(y, 0.f);
                    *(float2*)(C1 + row * ldc + col) = make_float2(rx, ry);
                    if (MODE == 2)
                        *(float2*)(C2 + row * ldc + col) =
                            make_float2(tf32r(rx), tf32r(ry));
                }
            }
        }
    }
}

// ---------------------------------------------------------------------------
// BN stats: 2D grid (48 col-blocks x 16 row-chunks), atomics into g_bnsum/sq.
// ---------------------------------------------------------------------------
__global__ void bn_stats_kernel(const float* __restrict__ agg,
                                const float* __restrict__ gen)
{
    const int c0 = blockIdx.x * 32;
    const int cx = threadIdx.x & 31;
    const int ry = threadIdx.x >> 5;   // 0..7
    const int c  = c0 + cx;

    const float* base;
    int stride;
    if (c0 < FEAT) { base = agg + c;          stride = FEAT; }
    else           { base = gen + (c - FEAT); stride = F2;   }

    const int r0 = blockIdx.y * 512;
    float sum = 0.f, sq = 0.f;
#pragma unroll 8
    for (int r = r0 + ry; r < r0 + 512; r += 8) {
        float v = base[(size_t)r * stride];
        sum += v; sq += v * v;
    }
    __shared__ float ssum[8][32], ssq[8][32];
    ssum[ry][cx] = sum; ssq[ry][cx] = sq;
    __syncthreads();
    if (ry == 0) {
#pragma unroll
        for (int r = 1; r < 8; r++) { sum += ssum[r][cx]; sq += ssq[r][cx]; }
        atomicAdd(&g_bnsum[c], sum);
        atomicAdd(&g_bnsq[c], sq);
    }
}

__global__ void bn_finalize(const float* __restrict__ gamma,
                            const float* __restrict__ beta)
{
    int c = blockIdx.x * blockDim.x + threadIdx.x;
    if (c >= F3) return;
    const float inv = 1.0f / (float)BATCH;
    float mean = g_bnsum[c] * inv;
    float var  = g_bnsq[c] * inv - mean * mean;
    float s = gamma[c] * rsqrtf(var + BN_EPS);
    g_s[c] = s;
    g_t[c] = beta[c] - mean * s;
}

// ---------------------------------------------------------------------------
extern "C" void kernel_launch(void* const* d_in, const int* in_sizes, int n_in,
                              void* d_out, int out_size)
{
    const float* feat  = (const float*)d_in[0];
    const float* Wg    = (const float*)d_in[1];
    const float* W1    = (const float*)d_in[2];
    const float* gamma = (const float*)d_in[3];
    const float* beta  = (const float*)d_in[4];
    const int*   neigh = (const int*)d_in[6];

    float* out   = (float*)d_out;
    float* aggO  = out + OFF_AGG;
    float* toO   = out + OFF_TO;
    float* genO  = out + OFF_GEN;
    float* rawO  = out + OFF_RAW;
    float* egenO = out + OFF_EGEN;
    float* erawO = out + OFF_ERAW;

    float *p_cat, *p_env, *p_genr, *p_WgT, *p_W1sT, *p_sum, *p_sq, *p_bias;
    cudaGetSymbolAddress((void**)&p_cat,  g_cat);
    cudaGetSymbolAddress((void**)&p_env,  g_env);
    cudaGetSymbolAddress((void**)&p_genr, g_genr);
    cudaGetSymbolAddress((void**)&p_WgT,  g_WgT);
    cudaGetSymbolAddress((void**)&p_W1sT, g_W1sT);
    cudaGetSymbolAddress((void**)&p_sum,  g_bnsum);
    cudaGetSymbolAddress((void**)&p_sq,   g_bnsq);
    cudaGetSymbolAddress((void**)&p_bias, g_bias);

    const int smem_bytes = NSTAGE * STAGE_BYTES;   // 221184
    cudaFuncSetAttribute(mma_gemm<0>, cudaFuncAttributeMaxDynamicSharedMemorySize, smem_bytes);
    cudaFuncSetAttribute(mma_gemm<1>, cudaFuncAttributeMaxDynamicSharedMemorySize, smem_bytes);
    cudaFuncSetAttribute(mma_gemm<2>, cudaFuncAttributeMaxDynamicSharedMemorySize, smem_bytes);

    // 0) W_gen -> K-major rounded; BN accumulator reset
    transpose_round<false><<<dim3(F2/32, F2/32), dim3(32, 8)>>>(Wg, p_WgT, F2, F2);
    cudaMemsetAsync(p_sum, 0, F3 * sizeof(float));
    cudaMemsetAsync(p_sq,  0, F3 * sizeof(float));

    // 1) gather + pooling (+tf32-rounded staging)
    gather_kernel<<<BATCH, 128>>>(feat, neigh, aggO);

    // 2) raw/gen = cat @ W_gen  [8192,1024]x[1024,1024]; also rounded gen
    mma_gemm<2><<<dim3(F2/BN, BATCH/BM), 256, smem_bytes>>>(
        p_cat, p_cat, p_WgT, rawO, genO, p_genr, nullptr,
        F2, F2, F2, F2, F2, F2);

    // 3) env_raw/env_gen = env @ W_gen[512:,:]   [8192,512]x[512,1024]
    mma_gemm<0><<<dim3(F2/BN, BATCH/BM), 256, smem_bytes>>>(
        p_env, p_env, p_WgT + FEAT, erawO, egenO, nullptr, nullptr,
        FEAT, FEAT, FEAT, FEAT, F2, F2);

    // 4) BN statistics + finalize
    bn_stats_kernel<<<dim3(F3/32, 16), 256>>>(aggO, genO);
    bn_finalize<<<F3/256, 256>>>(gamma, beta);

    // 5) fold BN into GEMM3: W1sT[n][k] = round(s_k * W1[k][n]); bias = t @ W1
    transpose_round<true><<<dim3(F3/32, F3/32), dim3(32, 8)>>>(W1, p_W1sT, F3, F3);
    bias_kernel<<<F3/32, 256>>>(W1);

    // 6) to_feats = relu([agg|gen]_r @ (sW1) + bias)   [8192,1536]x[1536,1536]
    mma_gemm<1><<<dim3(F3/BN, BATCH/BM), 256, smem_bytes>>>(
        p_cat + FEAT, p_genr, p_W1sT, toO, nullptr, nullptr, p_bias,
        F3, FEAT, F2, F2, F3, F3);

    (void)in_sizes; (void)n_in; (void)out_size;
}